// round 15
// baseline (speedup 1.0000x reference)
#include <cuda_runtime.h>
#include <cstdint>
#include <cstddef>

constexpr int B_ = 4, N_ = 2048, D_ = 64;
constexpr float L2E  = 1.4426950408889634f;   // log2(e)
constexpr float GLF  = 5.0f * L2E;            // gamma * log2e
constexpr float GT_F = GLF * 0.8f;
constexpr float GT_C = GLF * 0.7f;
constexpr float GT_P = GLF * 0.5f;
constexpr float P50  = 50.0f * L2E;
constexpr float IS3  = 0.57735026918962576f;  // 1/sqrt(3)

// ---------------------------------------------------------------------------
// Scratch (device globals -- allocation-free per harness rules)
// ---------------------------------------------------------------------------
__device__ float  g_nf[B_ * N_ * D_];
__device__ float4 g_f4[B_ * N_];        // normalized flow.xyz, 0
__device__ float4 g_p4[B_ * N_];        // pts.xyz, mask
__device__ float4 g_c4[B_ * N_];        // colors/255, label bits
__device__ float  g_fs[(size_t)B_ * N_ * N_];  // 64MB Gram scratch
__device__ float  g_rowA[B_ * N_];
__device__ float  g_rowSam[B_ * N_];
__device__ double g_pA[16], g_pV[16], g_pS[16];
__device__ unsigned g_cnt;

using ull = unsigned long long;

__device__ __forceinline__ void fma2(ull& d, ull a, ull b) {
    asm("fma.rn.f32x2 %0, %1, %2, %0;" : "+l"(d) : "l"(a), "l"(b));
}
__device__ __forceinline__ float2 unpack2(ull v) {
    float2 r;
    asm("mov.b64 {%0, %1}, %2;" : "=f"(r.x), "=f"(r.y) : "l"(v));
    return r;
}
__device__ __forceinline__ float ex2f(float x) {
    float r; asm("ex2.approx.f32 %0, %1;" : "=f"(r) : "f"(x)); return r;
}
__device__ __forceinline__ float rcpaf(float x) {
    float r; asm("rcp.approx.f32 %0, %1;" : "=f"(r) : "f"(x)); return r;
}
__device__ __forceinline__ float sqaf(float x) {
    float r; asm("sqrt.approx.f32 %0, %1;" : "=f"(r) : "f"(x)); return r;
}
// e^x for |x|<=1, degree-5 minimax, abs err ~4.5e-5. Runs on the FMA pipe.
__device__ __forceinline__ float expp(float x) {
    float r = fmaf(0.00868685f, x, 0.0437936f);
    r = fmaf(r, x, 0.1664888f);
    r = fmaf(r, x, 0.4991968f);
    r = fmaf(r, x, 1.0000228f);
    r = fmaf(r, x, 1.0000449f);
    return r;
}

// Two nops put k_gram at call-index 3 for the fixed `ncu -s 5 -c 1` capture.
__global__ void k_nop() {}

// ---------------------------------------------------------------------------
// Kernel 0: preprocess. One warp per point; aux loads spread over lanes 0-8.
// ---------------------------------------------------------------------------
__global__ void k_pre(const float* __restrict__ feat,
                      const float* __restrict__ flow,
                      const float* __restrict__ pts,
                      const int*   __restrict__ cols,
                      const int*   __restrict__ sam,
                      const unsigned char* __restrict__ mask) {
    int p    = blockIdx.x * (blockDim.x >> 5) + (threadIdx.x >> 5);
    int lane = threadIdx.x & 31;
    if (p >= B_ * N_) return;

    const float2 v = ((const float2*)(feat + (size_t)p * D_))[lane];
    float s = v.x * v.x + v.y * v.y;
    #pragma unroll
    for (int o = 16; o; o >>= 1) s += __shfl_xor_sync(0xffffffffu, s, o);
    float inv = 1.0f / (sqrtf(s) + 1e-7f);
    ((float2*)(g_nf + (size_t)p * D_))[lane] = make_float2(v.x * inv, v.y * inv);

    float aux = 0.f;
    if (lane < 3)      aux = flow[p * 3 + lane];
    else if (lane < 6) aux = pts[p * 3 + lane - 3];
    else if (lane < 9) aux = cols[p * 3 + lane - 6] * (1.0f / 255.0f);

    float fx = __shfl_sync(0xffffffffu, aux, 0);
    float fy = __shfl_sync(0xffffffffu, aux, 1);
    float fz = __shfl_sync(0xffffffffu, aux, 2);
    float px = __shfl_sync(0xffffffffu, aux, 3);
    float py = __shfl_sync(0xffffffffu, aux, 4);
    float pz = __shfl_sync(0xffffffffu, aux, 5);
    float cx = __shfl_sync(0xffffffffu, aux, 6);
    float cy = __shfl_sync(0xffffffffu, aux, 7);
    float cz = __shfl_sync(0xffffffffu, aux, 8);

    if (lane == 0) {
        float fi = 1.0f / (sqrtf(fx * fx + fy * fy + fz * fz) + 1e-20f);
        g_f4[p] = make_float4(fx * fi, fy * fi, fz * fi, 0.0f);
        g_p4[p] = make_float4(px, py, pz, mask[p] ? 1.0f : 0.0f);
        g_c4[p] = make_float4(cx, cy, cz, __int_as_float(sam[p]));
    }
}

// ---------------------------------------------------------------------------
// Kernel 1: Gram GEMM, 8x4 per-thread tile (block tile 128 rows x 64 cols),
//  symmetry: keep blocks with bx >= 2*by; mirror via register transpose.
//  sB swizzled (slot = (p&3)*16 + p>>2) so bv LDS.64 is one wavefront.
// ---------------------------------------------------------------------------
__global__ void __launch_bounds__(256) k_gram() {
    const int bx = blockIdx.x, by = blockIdx.y;
    if (bx < 2 * by) return;               // symmetric: mirrored by upper blocks
    const int b    = blockIdx.z;
    const int rowT = by * 128;
    const int colT = bx * 64;
    const int tid  = threadIdx.x;
    const int tx   = tid & 15, ty = tid >> 4;   // tx: 4 cols, ty: 8 rows

    __shared__ float2 sA[32][128];   // [k2][point], natural (reads broadcast)
    __shared__ float2 sB[32][64];    // [k2][slot],  swizzled

    const float4* nf4 = (const float4*)(g_nf + (size_t)b * N_ * D_);

    // load A tile: 128 points x 16 float4 = 2048 loads, 8 per thread
    {
        const int pA = tid & 127, kA = tid >> 7;   // kA 0..1
        #pragma unroll
        for (int l = 0; l < 8; l++) {
            int k4 = kA + 2 * l;
            float4 v = nf4[(size_t)(rowT + pA) * 16 + k4];
            sA[2 * k4][pA]     = make_float2(v.x, v.y);
            sA[2 * k4 + 1][pA] = make_float2(v.z, v.w);
        }
    }
    // load B tile: 64 points x 16 float4 = 1024 loads, 4 per thread
    {
        const int pB = tid & 63, kB = tid >> 6;    // kB 0..3
        const int sl = ((pB & 3) << 4) | (pB >> 2);
        #pragma unroll
        for (int l = 0; l < 4; l++) {
            int k4 = kB + 4 * l;
            float4 v = nf4[(size_t)(colT + pB) * 16 + k4];
            sB[2 * k4][sl]     = make_float2(v.x, v.y);
            sB[2 * k4 + 1][sl] = make_float2(v.z, v.w);
        }
    }
    __syncthreads();

    ull acc[8][4];
    #pragma unroll
    for (int i = 0; i < 8; i++)
        #pragma unroll
        for (int j = 0; j < 4; j++) acc[i][j] = 0ULL;

    #pragma unroll
    for (int k2 = 0; k2 < 32; k2++) {
        ull bv[4];
        #pragma unroll
        for (int j = 0; j < 4; j++)
            bv[j] = *(const ull*)&sB[k2][16 * j + tx];   // slot(4tx+j) = 16j+tx
        #pragma unroll
        for (int i = 0; i < 8; i++) {
            ull a = *(const ull*)&sA[k2][8 * ty + i];    // broadcast
            #pragma unroll
            for (int j = 0; j < 4; j++)
                fma2(acc[i][j], a, bv[j]);
        }
    }

    float fsv[8][4];
    #pragma unroll
    for (int i = 0; i < 8; i++)
        #pragma unroll
        for (int j = 0; j < 4; j++) {
            float2 u = unpack2(acc[i][j]);
            fsv[i][j] = u.x + u.y;
        }

    float* fsb = g_fs + (size_t)b * N_ * N_;
    const int row0 = rowT + 8 * ty, col0 = colT + 4 * tx;

    // direct stores (always valid: full dot products)
    #pragma unroll
    for (int i = 0; i < 8; i++) {
        float4 o = make_float4(fsv[i][0], fsv[i][1], fsv[i][2], fsv[i][3]);
        *(float4*)&fsb[(size_t)(row0 + i) * N_ + col0] = o;
    }

    if (bx >= 2 * by + 2) {
        // block entirely above diagonal: unconditional transposed mirror
        #pragma unroll
        for (int j = 0; j < 4; j++) {
            float4 t0 = make_float4(fsv[0][j], fsv[1][j], fsv[2][j], fsv[3][j]);
            float4 t1 = make_float4(fsv[4][j], fsv[5][j], fsv[6][j], fsv[7][j]);
            *(float4*)&fsb[(size_t)(col0 + j) * N_ + row0]     = t0;
            *(float4*)&fsb[(size_t)(col0 + j) * N_ + row0 + 4] = t1;
        }
    } else {
        // diagonal-straddling block: guarded scalar mirrors
        #pragma unroll
        for (int i = 0; i < 8; i++)
            #pragma unroll
            for (int j = 0; j < 4; j++)
                if (col0 + j > row0 + i)
                    fsb[(size_t)(col0 + j) * N_ + row0 + i] = fsv[i][j];
    }
}

// ---------------------------------------------------------------------------
// Kernel 2: epilogue + fused SAM pass. One warp per row.
// ---------------------------------------------------------------------------
__global__ void __launch_bounds__(256) k_epi(const int* __restrict__ sam) {
    const int b    = blockIdx.y;
    const int row0 = blockIdx.x * 8;
    const int w    = threadIdx.x >> 5;
    const int lane = threadIdx.x & 31;
    const int tid  = threadIdx.x;
    const int bn0  = b * N_;
    const int bn   = bn0 + row0 + w;

    __shared__ float4 sCF[64], sCP[64], sCC[64];

    const float4 fr = g_f4[bn], pr = g_p4[bn], cr = g_c4[bn];
    const int labr = __float_as_int(cr.w);
    const float* fsrow = g_fs + (size_t)bn * N_;

    float4 pF, pP, pC;
    if (tid < 64) { pF = g_f4[bn0 + tid]; pP = g_p4[bn0 + tid]; pC = g_c4[bn0 + tid]; }

    float acc[9];
    #pragma unroll
    for (int q = 0; q < 9; q++) acc[q] = 0.f;

    for (int ct = 0; ct < N_; ct += 64) {
        if (tid < 64) { sCF[tid] = pF; sCP[tid] = pP; sCC[tid] = pC; }
        __syncthreads();
        if (ct + 64 < N_ && tid < 64) {
            pF = g_f4[bn0 + ct + 64 + tid];
            pP = g_p4[bn0 + ct + 64 + tid];
            pC = g_c4[bn0 + ct + 64 + tid];
        }

        float fsv[2];
        fsv[0] = fsrow[ct + lane];
        fsv[1] = fsrow[ct + lane + 32];

        #pragma unroll
        for (int j = 0; j < 2; j++) {
            const int mc = lane + 32 * j;
            const float4 fm = sCF[mc], pm = sCP[mc], cm = sCC[mc];
            const float msk = pr.w * pm.w;
            const float fs = fsv[j];
            const float fc = fs * L2E;

            float fsim = (fr.x * fm.x + fr.y * fm.y + fr.z * fm.z) * msk;
            float dx = cr.x - cm.x, dy = cr.y - cm.y, dz = cr.z - cm.z;
            float d2 = fmaf(dx, dx, fmaf(dy, dy, dz * dz));
            float csim = (1.0f - sqaf(d2) * IS3) * msk;
            dx = pr.x - pm.x; dy = pr.y - pm.y; dz = pr.z - pm.z;
            float e2 = fmaf(dx, dx, fmaf(dy, dy, dz * dz));
            float psim = ex2f(-P50 * sqaf(e2)) * msk;

            const float emfs = expp(-fs);      // e^-fs on the FMA pipe
            float a, gp, ep;
            a  = ex2f(fmaf(-GLF, fsim, GT_F));
            gp = rcpaf(1.0f + a);
            ep = ex2f(fc * gp);
            acc[0] += ep; acc[1] = fmaf(emfs, ep, acc[1]);
            a  = ex2f(fmaf(-GLF, csim, GT_C));
            gp = rcpaf(1.0f + a);
            ep = ex2f(fc * gp);
            acc[2] += ep; acc[3] = fmaf(emfs, ep, acc[3]);
            a  = ex2f(fmaf(-GLF, psim, GT_P));
            gp = rcpaf(1.0f + a);
            ep = ex2f(fc * gp);
            acc[4] += ep; acc[5] = fmaf(emfs, ep, acc[5]);

            float efs = expp(fs);              // e^fs on the FMA pipe
            int labm = __float_as_int(cm.w);
            float pos = (labr == labm) ? 1.0f : 0.0f;
            acc[6] = fmaf(efs, 1.0f - pos, acc[6]);
            acc[7] += pos;
            acc[8] = fmaf(fs, pos, acc[8]);
        }
        __syncthreads();
    }

    #pragma unroll
    for (int q = 0; q < 9; q++)
        #pragma unroll
        for (int o = 16; o; o >>= 1)
            acc[q] += __shfl_xor_sync(0xffffffffu, acc[q], o);

    // ---- fused SAM pass: every lane holds neg/possum/posfs ----
    const float neg = acc[6];
    const int* labs = sam + bn0;
    float sacc = 0.f;
    #pragma unroll 4
    for (int c = 0; c < 64; c++) {
        int m = c * 32 + lane;
        float fs = fsrow[m];
        if (labs[m] == labr)
            sacc += __logf(__expf(fs) + neg);
    }
    #pragma unroll
    for (int o = 16; o; o >>= 1) sacc += __shfl_xor_sync(0xffffffffu, sacc, o);

    if (lane == 0) {
        float lpp = __logf(1.0f + acc[0]) + __logf(1.0f + acc[1])
                  + __logf(1.0f + acc[2]) + __logf(1.0f + acc[3])
                  + __logf(1.0f + acc[4]) + __logf(1.0f + acc[5]);
        g_rowA[bn]   = lpp * pr.w;
        g_rowSam[bn] = (sacc - acc[8]) / acc[7];
    }
}

// ---------------------------------------------------------------------------
// Kernel 3: fused final reduction. Counter self-resets for graph replays.
// ---------------------------------------------------------------------------
__global__ void __launch_bounds__(512) k_fin(const unsigned char* __restrict__ mask,
                                             float* __restrict__ out) {
    const int i = blockIdx.x * 512 + threadIdx.x;
    double a = (double)g_rowA[i];
    double v = mask[i] ? 1.0 : 0.0;
    double s = (double)g_rowSam[i];
    #pragma unroll
    for (int o = 16; o; o >>= 1) {
        a += __shfl_xor_sync(0xffffffffu, a, o);
        v += __shfl_xor_sync(0xffffffffu, v, o);
        s += __shfl_xor_sync(0xffffffffu, s, o);
    }
    __shared__ double sh[3][16];
    __shared__ bool last;
    const int w = threadIdx.x >> 5, lane = threadIdx.x & 31;
    if (lane == 0) { sh[0][w] = a; sh[1][w] = v; sh[2][w] = s; }
    __syncthreads();
    if (threadIdx.x == 0) {
        double xa = 0, xv = 0, xs = 0;
        #pragma unroll
        for (int k = 0; k < 16; k++) { xa += sh[0][k]; xv += sh[1][k]; xs += sh[2][k]; }
        g_pA[blockIdx.x] = xa; g_pV[blockIdx.x] = xv; g_pS[blockIdx.x] = xs;
        __threadfence();
        unsigned t = atomicAdd(&g_cnt, 1u);
        last = (t == 15u);
    }
    __syncthreads();
    if (last && threadIdx.x == 0) {
        double A[4] = {0, 0, 0, 0}, V[4] = {0, 0, 0, 0}, S = 0.0;
        #pragma unroll
        for (int k = 0; k < 16; k++) {
            A[k >> 2] += g_pA[k];
            V[k >> 2] += g_pV[k];
            S         += g_pS[k];
        }
        double core = A[0] / V[0] + A[1] / V[1] + A[2] / V[2] + A[3] / V[3];
        out[0] = (float)(-core / (double)B_ + S / ((double)B_ * (double)N_));
        g_cnt = 0;   // reset for next graph replay
    }
}

// ---------------------------------------------------------------------------
// Launcher -- k_gram at call-index 3 for the ncu capture window.
// ---------------------------------------------------------------------------
extern "C" void kernel_launch(void* const* d_in, const int* in_sizes, int n_in,
                              void* d_out, int out_size) {
    const float* feat = (const float*)d_in[0];
    const float* flow = (const float*)d_in[1];
    const float* pts  = (const float*)d_in[2];
    const int*   cols = (const int*)d_in[3];
    const int*   sam  = (const int*)d_in[4];
    const unsigned char* mask = (const unsigned char*)d_in[5];

    k_pre<<<(B_ * N_) / 8, 256>>>(feat, flow, pts, cols, sam, mask);
    k_nop<<<1, 32>>>();
    k_nop<<<1, 32>>>();
    dim3 gg(N_ / 64, N_ / 128, B_);
    k_gram<<<gg, 256>>>();
    dim3 ge(N_ / 8, B_);
    k_epi<<<ge, 256>>>(sam);
    k_fin<<<16, 512>>>(mask, (float*)d_out);
}

// round 17
// speedup vs baseline: 1.0403x; 1.0403x over previous
#include <cuda_runtime.h>
#include <cstdint>
#include <cstddef>

constexpr int B_ = 4, N_ = 2048, D_ = 64;
constexpr float L2E  = 1.4426950408889634f;   // log2(e)
constexpr float GLF  = 5.0f * L2E;            // gamma * log2e
constexpr float GT_F = GLF * 0.8f;
constexpr float GT_C = GLF * 0.7f;
constexpr float GT_P = GLF * 0.5f;
constexpr float P50  = 50.0f * L2E;
constexpr float IS3  = 0.57735026918962576f;  // 1/sqrt(3)

// ---------------------------------------------------------------------------
// Scratch (device globals -- allocation-free per harness rules)
// ---------------------------------------------------------------------------
__device__ float  g_nf[B_ * N_ * D_];
__device__ float4 g_f4[B_ * N_];        // normalized flow.xyz, 0
__device__ float4 g_p4[B_ * N_];        // pts.xyz, mask
__device__ float4 g_c4[B_ * N_];        // colors/255, label bits
__device__ float  g_fs[(size_t)B_ * N_ * N_];   // 64MB Gram scratch
__device__ float  g_part[(size_t)B_ * 32 * N_ * 6];  // 6.3MB channel partials
__device__ float  g_rowA[B_ * N_];
__device__ float  g_rowSam[B_ * N_];
__device__ double g_pA[16], g_pV[16], g_pS[16];
__device__ unsigned g_cnt;

using ull = unsigned long long;

__device__ __forceinline__ void fma2(ull& d, ull a, ull b) {
    asm("fma.rn.f32x2 %0, %1, %2, %0;" : "+l"(d) : "l"(a), "l"(b));
}
__device__ __forceinline__ float2 unpack2(ull v) {
    float2 r;
    asm("mov.b64 {%0, %1}, %2;" : "=f"(r.x), "=f"(r.y) : "l"(v));
    return r;
}
__device__ __forceinline__ float ex2f(float x) {
    float r; asm("ex2.approx.f32 %0, %1;" : "=f"(r) : "f"(x)); return r;
}
__device__ __forceinline__ float rcpaf(float x) {
    float r; asm("rcp.approx.f32 %0, %1;" : "=f"(r) : "f"(x)); return r;
}
__device__ __forceinline__ float sqaf(float x) {
    float r; asm("sqrt.approx.f32 %0, %1;" : "=f"(r) : "f"(x)); return r;
}
// e^x for |x|<=1, degree-5 minimax, abs err ~4.5e-5. Runs on the FMA pipe.
__device__ __forceinline__ float expp(float x) {
    float r = fmaf(0.00868685f, x, 0.0437936f);
    r = fmaf(r, x, 0.1664888f);
    r = fmaf(r, x, 0.4991968f);
    r = fmaf(r, x, 1.0000228f);
    r = fmaf(r, x, 1.0000449f);
    return r;
}

// One nop puts k_epi_t at call-index 3 for the fixed `ncu -s 5 -c 1` capture.
__global__ void k_nop() {}

// ---------------------------------------------------------------------------
// Kernel 0: preprocess. One warp per point; aux loads spread over lanes 0-8.
// ---------------------------------------------------------------------------
__global__ void k_pre(const float* __restrict__ feat,
                      const float* __restrict__ flow,
                      const float* __restrict__ pts,
                      const int*   __restrict__ cols,
                      const int*   __restrict__ sam,
                      const unsigned char* __restrict__ mask) {
    int p    = blockIdx.x * (blockDim.x >> 5) + (threadIdx.x >> 5);
    int lane = threadIdx.x & 31;
    if (p >= B_ * N_) return;

    const float2 v = ((const float2*)(feat + (size_t)p * D_))[lane];
    float s = v.x * v.x + v.y * v.y;
    #pragma unroll
    for (int o = 16; o; o >>= 1) s += __shfl_xor_sync(0xffffffffu, s, o);
    float inv = 1.0f / (sqrtf(s) + 1e-7f);
    ((float2*)(g_nf + (size_t)p * D_))[lane] = make_float2(v.x * inv, v.y * inv);

    float aux = 0.f;
    if (lane < 3)      aux = flow[p * 3 + lane];
    else if (lane < 6) aux = pts[p * 3 + lane - 3];
    else if (lane < 9) aux = cols[p * 3 + lane - 6] * (1.0f / 255.0f);

    float fx = __shfl_sync(0xffffffffu, aux, 0);
    float fy = __shfl_sync(0xffffffffu, aux, 1);
    float fz = __shfl_sync(0xffffffffu, aux, 2);
    float px = __shfl_sync(0xffffffffu, aux, 3);
    float py = __shfl_sync(0xffffffffu, aux, 4);
    float pz = __shfl_sync(0xffffffffu, aux, 5);
    float cx = __shfl_sync(0xffffffffu, aux, 6);
    float cy = __shfl_sync(0xffffffffu, aux, 7);
    float cz = __shfl_sync(0xffffffffu, aux, 8);

    if (lane == 0) {
        float fi = 1.0f / (sqrtf(fx * fx + fy * fy + fz * fz) + 1e-20f);
        g_f4[p] = make_float4(fx * fi, fy * fi, fz * fi, 0.0f);
        g_p4[p] = make_float4(px, py, pz, mask[p] ? 1.0f : 0.0f);
        g_c4[p] = make_float4(cx, cy, cz, __int_as_float(sam[p]));
    }
}

// ---------------------------------------------------------------------------
// Kernel 1: Gram GEMM (proven R13 config). 64x64 tile, 4x4 per thread,
//  symmetry with register-transposed mirror stores.
// ---------------------------------------------------------------------------
__global__ void __launch_bounds__(256) k_gram() {
    if (blockIdx.y > blockIdx.x) return;   // symmetric: lower tri mirrored
    const int b    = blockIdx.z;
    const int rowT = blockIdx.y * 64;
    const int colT = blockIdx.x * 64;
    const int tid  = threadIdx.x;
    const int tx   = tid & 15, ty = tid >> 4;

    __shared__ float2 sA[32][4][16];   // [k2][p&3][p>>2]
    __shared__ float2 sB[32][4][16];

    const float4* nf4 = (const float4*)(g_nf + (size_t)b * N_ * D_);
    const int lm = tid & 63, lk4 = tid >> 6;   // lk4 0..3
    const int lq = lm & 3,  lt = lm >> 2;

    #pragma unroll
    for (int l = 0; l < 4; l++) {
        int k4 = lk4 + 4 * l;
        float4 va = nf4[(size_t)(rowT + lm) * 16 + k4];
        sA[2 * k4][lq][lt]     = make_float2(va.x, va.y);
        sA[2 * k4 + 1][lq][lt] = make_float2(va.z, va.w);
        float4 vb = nf4[(size_t)(colT + lm) * 16 + k4];
        sB[2 * k4][lq][lt]     = make_float2(vb.x, vb.y);
        sB[2 * k4 + 1][lq][lt] = make_float2(vb.z, vb.w);
    }
    __syncthreads();

    ull fs2[16];
    #pragma unroll
    for (int q = 0; q < 16; q++) fs2[q] = 0ULL;

    #pragma unroll
    for (int k2 = 0; k2 < 32; k2++) {
        ull av[4], bv[4];
        #pragma unroll
        for (int i = 0; i < 4; i++) av[i] = *(const ull*)&sA[k2][i][ty];
        #pragma unroll
        for (int j = 0; j < 4; j++) bv[j] = *(const ull*)&sB[k2][j][tx];
        #pragma unroll
        for (int i = 0; i < 4; i++)
            #pragma unroll
            for (int j = 0; j < 4; j++)
                fma2(fs2[i * 4 + j], av[i], bv[j]);
    }

    float fsv[4][4];
    #pragma unroll
    for (int i = 0; i < 4; i++)
        #pragma unroll
        for (int j = 0; j < 4; j++) {
            float2 u = unpack2(fs2[i * 4 + j]);
            fsv[i][j] = u.x + u.y;
        }

    float* fsb = g_fs + (size_t)b * N_ * N_;
    const int row0 = rowT + 4 * ty, col0 = colT + 4 * tx;

    #pragma unroll
    for (int i = 0; i < 4; i++) {
        float4 o = make_float4(fsv[i][0], fsv[i][1], fsv[i][2], fsv[i][3]);
        *(float4*)&fsb[(size_t)(row0 + i) * N_ + col0] = o;
    }
    if (rowT != colT) {
        #pragma unroll
        for (int j = 0; j < 4; j++) {
            float4 t = make_float4(fsv[0][j], fsv[1][j], fsv[2][j], fsv[3][j]);
            *(float4*)&fsb[(size_t)(col0 + j) * N_ + row0] = t;
        }
    }
}

// ---------------------------------------------------------------------------
// Kernel 2: symmetric tiled epilogue. 528 upper tiles per batch (rb<=cb),
//  each pair's 6 within-sample channel values computed ONCE and accumulated
//  into row sums (band rb, slot cb) and -- off-diagonal -- col sums (band cb,
//  slot rb). Deterministic per-band partials in g_part; no atomics.
// ---------------------------------------------------------------------------
__global__ void __launch_bounds__(256) k_epi_t() {
    const int b = blockIdx.y;
    int t = blockIdx.x, rb = 0;
    while (t >= 32 - rb) { t -= 32 - rb; rb++; }
    const int cb = rb + t;

    const int tid = threadIdx.x;
    const int tx  = tid & 15, ty = tid >> 4;
    const int bn0 = b * N_;
    const int rowT = rb * 64, colT = cb * 64;

    __shared__ float4 sRF[64], sRP[64], sRC[64];
    __shared__ float4 sCF[64], sCP[64], sCC[64];
    __shared__ float  sStage[8][16][4][6];      // 12.3KB col-sum staging

    if (tid < 64) {
        sRF[tid] = g_f4[bn0 + rowT + tid];
        sRP[tid] = g_p4[bn0 + rowT + tid];
        sRC[tid] = g_c4[bn0 + rowT + tid];
        sCF[tid] = g_f4[bn0 + colT + tid];
        sCP[tid] = g_p4[bn0 + colT + tid];
        sCC[tid] = g_c4[bn0 + colT + tid];
    }
    __syncthreads();

    float racc[4][6], cacc[4][6];
    #pragma unroll
    for (int i = 0; i < 4; i++)
        #pragma unroll
        for (int q = 0; q < 6; q++) { racc[i][q] = 0.f; cacc[i][q] = 0.f; }

    const float* fsb = g_fs + (size_t)b * N_ * N_;

    #pragma unroll
    for (int i = 0; i < 4; i++) {
        const int Rl = 4 * ty + i;
        const float4 fr = sRF[Rl], pr = sRP[Rl], cr = sRC[Rl];
        float4 f4 = *(const float4*)&fsb[(size_t)(rowT + Rl) * N_ + colT + 4 * tx];
        float fsa[4] = {f4.x, f4.y, f4.z, f4.w};
        #pragma unroll
        for (int j = 0; j < 4; j++) {
            const int Cl = 4 * tx + j;
            const float4 fm = sCF[Cl], pm = sCP[Cl], cm = sCC[Cl];
            const float msk = pr.w * pm.w;
            const float fs = fsa[j];
            const float fc = fs * L2E;

            float fsim = (fr.x * fm.x + fr.y * fm.y + fr.z * fm.z) * msk;
            float dx = cr.x - cm.x, dy = cr.y - cm.y, dz = cr.z - cm.z;
            float d2 = fmaf(dx, dx, fmaf(dy, dy, dz * dz));
            float csim = (1.0f - sqaf(d2) * IS3) * msk;
            dx = pr.x - pm.x; dy = pr.y - pm.y; dz = pr.z - pm.z;
            float e2 = fmaf(dx, dx, fmaf(dy, dy, dz * dz));
            float psim = ex2f(-P50 * sqaf(e2)) * msk;

            const float emfs = expp(-fs);
            float a, gp, ep;
            a  = ex2f(fmaf(-GLF, fsim, GT_F));
            gp = rcpaf(1.0f + a);
            ep = ex2f(fc * gp);
            racc[i][0] += ep; racc[i][1] = fmaf(emfs, ep, racc[i][1]);
            cacc[j][0] += ep; cacc[j][1] = fmaf(emfs, ep, cacc[j][1]);
            a  = ex2f(fmaf(-GLF, csim, GT_C));
            gp = rcpaf(1.0f + a);
            ep = ex2f(fc * gp);
            racc[i][2] += ep; racc[i][3] = fmaf(emfs, ep, racc[i][3]);
            cacc[j][2] += ep; cacc[j][3] = fmaf(emfs, ep, cacc[j][3]);
            a  = ex2f(fmaf(-GLF, psim, GT_P));
            gp = rcpaf(1.0f + a);
            ep = ex2f(fc * gp);
            racc[i][4] += ep; racc[i][5] = fmaf(emfs, ep, racc[i][5]);
            cacc[j][4] += ep; cacc[j][5] = fmaf(emfs, ep, cacc[j][5]);
        }
    }

    // ---- row sums: reduce across tx (butterfly over tx bits, in-warp) ----
    #pragma unroll
    for (int i = 0; i < 4; i++)
        #pragma unroll
        for (int q = 0; q < 6; q++)
            #pragma unroll
            for (int o = 8; o; o >>= 1)
                racc[i][q] += __shfl_xor_sync(0xffffffffu, racc[i][q], o);

    if (tx == 0) {
        #pragma unroll
        for (int i = 0; i < 4; i++) {
            float* dst = g_part + ((size_t)(b * 32 + cb) * N_ + rowT + 4 * ty + i) * 6;
            #pragma unroll
            for (int q = 0; q < 6; q++) dst[q] = racc[i][q];
        }
    }

    // ---- col sums (off-diagonal only): these are row sums for band cb ----
    if (rb != cb) {
        #pragma unroll
        for (int j = 0; j < 4; j++)
            #pragma unroll
            for (int q = 0; q < 6; q++)
                cacc[j][q] += __shfl_xor_sync(0xffffffffu, cacc[j][q], 16);
        const int w = tid >> 5;
        if ((ty & 1) == 0) {
            #pragma unroll
            for (int j = 0; j < 4; j++)
                #pragma unroll
                for (int q = 0; q < 6; q++)
                    sStage[w][tx][j][q] = cacc[j][q];
        }
        __syncthreads();
        if (tid < 64) {
            float s[6] = {0.f, 0.f, 0.f, 0.f, 0.f, 0.f};
            #pragma unroll
            for (int w2 = 0; w2 < 8; w2++)
                #pragma unroll
                for (int q = 0; q < 6; q++)
                    s[q] += sStage[w2][tid >> 2][tid & 3][q];
            float* dst = g_part + ((size_t)(b * 32 + rb) * N_ + colT + tid) * 6;
            #pragma unroll
            for (int q = 0; q < 6; q++) dst[q] = s[q];
        }
    }
}

// ---------------------------------------------------------------------------
// Kernel 3: per-row finisher. Sums the 32 channel partials, computes the SAM
//  accumulators (neg/possum/posfs) + positive-pair log term from the fs row,
//  writes rowA / rowSam. One warp per row.
// ---------------------------------------------------------------------------
__global__ void __launch_bounds__(256) k_sam2(const int* __restrict__ sam) {
    const int w    = threadIdx.x >> 5;
    const int lane = threadIdx.x & 31;
    const int bn   = blockIdx.x * 8 + w;
    const int b    = bn >> 11;
    const int n    = bn & (N_ - 1);

    // gather the 32 slot partials (lane = slot)
    float acc6[6];
    {
        const float* src = g_part + ((size_t)(b * 32 + lane) * N_ + n) * 6;
        #pragma unroll
        for (int q = 0; q < 6; q++) acc6[q] = src[q];
    }
    #pragma unroll
    for (int q = 0; q < 6; q++)
        #pragma unroll
        for (int o = 16; o; o >>= 1)
            acc6[q] += __shfl_xor_sync(0xffffffffu, acc6[q], o);

    const float* fsrow = g_fs + (size_t)bn * N_;
    const int* labs = sam + b * N_;
    const int labn = sam[bn];

    float neg = 0.f, psum = 0.f, pfs = 0.f;
    #pragma unroll 4
    for (int c = 0; c < 64; c++) {
        int m = c * 32 + lane;
        float fs = fsrow[m];
        if (labs[m] == labn) { psum += 1.0f; pfs += fs; }
        else                 { neg += __expf(fs); }
    }
    #pragma unroll
    for (int o = 16; o; o >>= 1) {
        neg  += __shfl_xor_sync(0xffffffffu, neg,  o);
        psum += __shfl_xor_sync(0xffffffffu, psum, o);
        pfs  += __shfl_xor_sync(0xffffffffu, pfs,  o);
    }

    float sacc = 0.f;
    #pragma unroll 4
    for (int c = 0; c < 64; c++) {
        int m = c * 32 + lane;
        if (labs[m] == labn)
            sacc += __logf(__expf(fsrow[m]) + neg);
    }
    #pragma unroll
    for (int o = 16; o; o >>= 1) sacc += __shfl_xor_sync(0xffffffffu, sacc, o);

    if (lane == 0) {
        float lpp = __logf(1.0f + acc6[0]) + __logf(1.0f + acc6[1])
                  + __logf(1.0f + acc6[2]) + __logf(1.0f + acc6[3])
                  + __logf(1.0f + acc6[4]) + __logf(1.0f + acc6[5]);
        g_rowA[bn]   = lpp * g_p4[bn].w;
        g_rowSam[bn] = (sacc - pfs) / psum;
    }
}

// ---------------------------------------------------------------------------
// Kernel 4: fused final reduction. Counter self-resets for graph replays.
// ---------------------------------------------------------------------------
__global__ void __launch_bounds__(512) k_fin(const unsigned char* __restrict__ mask,
                                             float* __restrict__ out) {
    const int i = blockIdx.x * 512 + threadIdx.x;
    double a = (double)g_rowA[i];
    double v = mask[i] ? 1.0 : 0.0;
    double s = (double)g_rowSam[i];
    #pragma unroll
    for (int o = 16; o; o >>= 1) {
        a += __shfl_xor_sync(0xffffffffu, a, o);
        v += __shfl_xor_sync(0xffffffffu, v, o);
        s += __shfl_xor_sync(0xffffffffu, s, o);
    }
    __shared__ double sh[3][16];
    __shared__ bool last;
    const int w = threadIdx.x >> 5, lane = threadIdx.x & 31;
    if (lane == 0) { sh[0][w] = a; sh[1][w] = v; sh[2][w] = s; }
    __syncthreads();
    if (threadIdx.x == 0) {
        double xa = 0, xv = 0, xs = 0;
        #pragma unroll
        for (int k = 0; k < 16; k++) { xa += sh[0][k]; xv += sh[1][k]; xs += sh[2][k]; }
        g_pA[blockIdx.x] = xa; g_pV[blockIdx.x] = xv; g_pS[blockIdx.x] = xs;
        __threadfence();
        unsigned t = atomicAdd(&g_cnt, 1u);
        last = (t == 15u);
    }
    __syncthreads();
    if (last && threadIdx.x == 0) {
        double A[4] = {0, 0, 0, 0}, V[4] = {0, 0, 0, 0}, S = 0.0;
        #pragma unroll
        for (int k = 0; k < 16; k++) {
            A[k >> 2] += g_pA[k];
            V[k >> 2] += g_pV[k];
            S         += g_pS[k];
        }
        double core = A[0] / V[0] + A[1] / V[1] + A[2] / V[2] + A[3] / V[3];
        out[0] = (float)(-core / (double)B_ + S / ((double)B_ * (double)N_));
        g_cnt = 0;   // reset for next graph replay
    }
}

// ---------------------------------------------------------------------------
// Launcher -- k_epi_t at call-index 3 for the ncu capture window.
// ---------------------------------------------------------------------------
extern "C" void kernel_launch(void* const* d_in, const int* in_sizes, int n_in,
                              void* d_out, int out_size) {
    const float* feat = (const float*)d_in[0];
    const float* flow = (const float*)d_in[1];
    const float* pts  = (const float*)d_in[2];
    const int*   cols = (const int*)d_in[3];
    const int*   sam  = (const int*)d_in[4];
    const unsigned char* mask = (const unsigned char*)d_in[5];

    k_pre<<<(B_ * N_) / 8, 256>>>(feat, flow, pts, cols, sam, mask);
    k_nop<<<1, 32>>>();
    dim3 gg(N_ / 64, N_ / 64, B_);
    k_gram<<<gg, 256>>>();
    dim3 ge(528, B_);
    k_epi_t<<<ge, 256>>>();
    k_sam2<<<(B_ * N_) / 8, 256>>>(sam);
    k_fin<<<16, 512>>>(mask, (float*)d_out);
}